// round 15
// baseline (speedup 1.0000x reference)
#include <cuda_runtime.h>
#include <cstdint>

// img:  (1, 64, 64, 1024) float32
// rois: (1, 1024, 4) int32  -> x, y, w, h
// out:  (1, 1024, 7, 7, 1024) float32
//
// One CTA per (roi, py); 256 threads, one float4 channel lane each.
// Loads: R11 block-uniform 3-path dedup (w<=2 / ydup / general), batched
// independent __ldg. Stores: staged in SMEM (28KB contiguous per row) and
// written with ONE 1D TMA bulk store (cp.async.bulk.global.shared::cta),
// removing all STG wavefronts from the L1tex path (measured invariant
// bottleneck) and overlapping the write stream on the TMA engine.

#define POOL 7
#define HW 64
#define CV 256   // float4 lanes per pixel

__device__ __forceinline__ float4 lerp2d(float4 ta, float4 tb, float4 ba, float4 bb,
                                         float wmtx, float wtx, float wmty, float wty)
{
    float4 res;
    res.x = (ta.x * wmtx + tb.x * wtx) * wmty + (ba.x * wmtx + bb.x * wtx) * wty;
    res.y = (ta.y * wmtx + tb.y * wtx) * wmty + (ba.y * wmtx + bb.y * wtx) * wty;
    res.z = (ta.z * wmtx + tb.z * wtx) * wmty + (ba.z * wmtx + bb.z * wtx) * wty;
    res.w = (ta.w * wmtx + tb.w * wtx) * wmty + (ba.w * wmtx + bb.w * wtx) * wty;
    return res;
}

__device__ __forceinline__ float4 sel4(int p, float4 a, float4 b)
{
    float4 r;
    r.x = p ? a.x : b.x;
    r.y = p ? a.y : b.y;
    r.z = p ? a.z : b.z;
    r.w = p ? a.w : b.w;
    return r;
}

__global__ __launch_bounds__(256, 4) void roi_pool_kernel(
    const float* __restrict__ img_,
    const int* __restrict__ rois,
    float* __restrict__ out_)
{
    __shared__ __align__(128) float4 stage[POOL * CV];   // 28 KB

    const float4* __restrict__ img = reinterpret_cast<const float4*>(img_);

    const int py  = blockIdx.x;   // 0..6
    const int roi = blockIdx.y;   // 0..1023

    const int4 r = reinterpret_cast<const int4*>(rois)[roi];
    const int rx = r.x, ry = r.y, rw = r.z, rh = r.w;

    // ---- y axis (once per block) ----
    const float sy   = (float)rh / (float)POOL;
    const float srcy = ((float)py + 0.5f) * sy - 0.5f;
    const float fy   = floorf(srcy);
    const float ty   = srcy - fy;
    const int ylo = min(max((int)fy,     0), rh - 1);
    const int yhi = min(max((int)fy + 1, 0), rh - 1);
    const int noty = (yhi != ylo);

    const float4* __restrict__ rowT = img + (size_t)((ry + ylo) * HW) * CV;
    const float4* __restrict__ rowB = img + (size_t)((ry + yhi) * HW) * CV;

    const int c = threadIdx.x;

    const float sx   = (float)rw / (float)POOL;
    const float wty  = ty;
    const float wmty = 1.0f - ty;

    // ---- x coords / weights (block-uniform, precomputed) ----
    int xA[POOL], xB[POOL];
    float wx[POOL];
    #pragma unroll
    for (int px = 0; px < POOL; px++) {
        const float srcx = ((float)px + 0.5f) * sx - 0.5f;
        const float fx   = floorf(srcx);
        wx[px] = srcx - fx;
        const int xlo = min(max((int)fx,     0), rw - 1);
        const int xhi = min(max((int)fx + 1, 0), rw - 1);
        xA[px] = rx + xlo;
        xB[px] = rx + xhi;
    }

    if (rw <= 2) {
        // ---- path A: at most 2 unique columns: rx and rx+rw-1 ----
        const size_t q0 = (size_t)rx * CV + c;
        const size_t q1 = (size_t)(rx + rw - 1) * CV + c;
        const float4 t0 = __ldg(rowT + q0);
        const float4 t1 = __ldg(rowT + q1);
        float4 b0, b1;
        if (noty) {
            b0 = __ldg(rowB + q0);
            b1 = __ldg(rowB + q1);
        } else {
            b0 = t0;
            b1 = t1;
        }
        #pragma unroll
        for (int px = 0; px < POOL; px++) {
            const float wtx  = wx[px];
            const float wmtx = 1.0f - wtx;
            const int selA = (xA[px] != rx);
            const int selB = (xB[px] != rx);
            const float4 ta = sel4(selA, t1, t0);
            const float4 tb = sel4(selB, t1, t0);
            const float4 ba = sel4(selA, b1, b0);
            const float4 bb = sel4(selB, b1, b0);
            stage[px * CV + c] = lerp2d(ta, tb, ba, bb, wmtx, wtx, wmty, wty);
        }
    } else if (!noty) {
        // ---- path B: bottom row == top row; x-lerp only ----
        #pragma unroll
        for (int px = 0; px < POOL; px++) {
            const float4 ta = __ldg(rowT + (size_t)xA[px] * CV + c);
            const float4 tb = __ldg(rowT + (size_t)xB[px] * CV + c);
            const float wtx  = wx[px];
            const float wmtx = 1.0f - wtx;
            float4 top;
            top.x = ta.x * wmtx + tb.x * wtx;
            top.y = ta.y * wmtx + tb.y * wtx;
            top.z = ta.z * wmtx + tb.z * wtx;
            top.w = ta.w * wmtx + tb.w * wtx;
            float4 res;
            res.x = top.x * wmty + top.x * wty;
            res.y = top.y * wmty + top.y * wty;
            res.z = top.z * wmty + top.z * wty;
            res.w = top.w * wmty + top.w * wty;
            stage[px * CV + c] = res;
        }
    } else {
        // ---- path C: general batched 28-load loop ----
        #pragma unroll
        for (int px = 0; px < POOL; px++) {
            const float4 ta = __ldg(rowT + (size_t)xA[px] * CV + c);
            const float4 tb = __ldg(rowT + (size_t)xB[px] * CV + c);
            const float4 ba = __ldg(rowB + (size_t)xA[px] * CV + c);
            const float4 bb = __ldg(rowB + (size_t)xB[px] * CV + c);
            const float wtx  = wx[px];
            const float wmtx = 1.0f - wtx;
            stage[px * CV + c] = lerp2d(ta, tb, ba, bb, wmtx, wtx, wmty, wty);
        }
    }

    __syncthreads();

    // ---- one 1D TMA bulk store: 28KB SMEM -> contiguous GMEM row ----
    if (threadIdx.x == 0) {
        asm volatile("fence.proxy.async.shared::cta;" ::: "memory");
        const uint32_t s = (uint32_t)__cvta_generic_to_shared(stage);
        float* dst = out_ + ((size_t)roi * (POOL * POOL) + (size_t)py * POOL) * (CV * 4);
        asm volatile(
            "cp.async.bulk.global.shared::cta.bulk_group [%0], [%1], %2;"
            :: "l"(dst), "r"(s), "n"(POOL * CV * 16) : "memory");
        asm volatile("cp.async.bulk.commit_group;" ::: "memory");
        asm volatile("cp.async.bulk.wait_group 0;" ::: "memory");
    }
}

extern "C" void kernel_launch(void* const* d_in, const int* in_sizes, int n_in,
                              void* d_out, int out_size)
{
    const float* img  = (const float*)d_in[0];
    const int*   rois = (const int*)d_in[1];
    float*       out  = (float*)d_out;

    dim3 grid(POOL, 1024);
    roi_pool_kernel<<<grid, 256>>>(img, rois, out);
}